// round 1
// baseline (speedup 1.0000x reference)
#include <cuda_runtime.h>

// Problem constants
#define BATCH 8
#define N_SEQ 1024
#define CDIM  256
#define RREL  16

// Scratch (device globals — no allocation allowed)
__device__ __align__(16) float g_Gt[CDIM * CDIM];      // Gt[m][k] = sum_c Wq[c][k]*Wk[c][m]
__device__ __align__(16) float g_wu[CDIM];             // Wq^T @ b_k
__device__ __align__(16) float g_wv[CDIM];             // Wk^T @ b_q
__device__ float g_cst;                                // b_q . b_k
__device__ __align__(16) float g_A[BATCH * N_SEQ * CDIM];  // Q @ G   (8 MB)
__device__ __align__(16) float g_u[BATCH * N_SEQ];
__device__ __align__(16) float g_v[BATCH * N_SEQ];

// ---------------------------------------------------------------------------
// prep_gt: Gt[m][k] = sum_c Wq[c][k] * Wk[c][m]   (256x256x256 small GEMM)
// grid: 256 blocks (16x16 tiles of 16x16), 256 threads
// ---------------------------------------------------------------------------
__global__ void prep_gt(const float* __restrict__ Wq, const float* __restrict__ Wk) {
    int bx = blockIdx.x;
    int mt = bx >> 4;       // m tile
    int kt = bx & 15;       // k tile
    int tid = threadIdx.x;
    int tm = tid >> 4;
    int tk = tid & 15;
    int lc = tid >> 4;      // loader: c-row within chunk
    int li = tid & 15;      // loader: col within tile

    __shared__ float sq[16][16];  // [c][k]
    __shared__ float sk[16][16];  // [c][m]

    float acc = 0.f;
    for (int c0 = 0; c0 < CDIM; c0 += 16) {
        sq[lc][li] = Wq[(c0 + lc) * CDIM + kt * 16 + li];
        sk[lc][li] = Wk[(c0 + lc) * CDIM + mt * 16 + li];
        __syncthreads();
#pragma unroll
        for (int cc = 0; cc < 16; cc++)
            acc += sq[cc][tk] * sk[cc][tm];
        __syncthreads();
    }
    g_Gt[(mt * 16 + tm) * CDIM + kt * 16 + tk] = acc;
}

// ---------------------------------------------------------------------------
// prep_vec: wu[k] = sum_c Wq[c][k]*bk[c]; wv[m] = sum_c Wk[c][m]*bq[c]; cst = bq.bk
// 1 block, 256 threads
// ---------------------------------------------------------------------------
__global__ void prep_vec(const float* __restrict__ Wq, const float* __restrict__ Wk,
                         const float* __restrict__ bq, const float* __restrict__ bk) {
    int tid = threadIdx.x;
    float su = 0.f, sv = 0.f;
    for (int c = 0; c < CDIM; c++) {
        su += Wq[c * CDIM + tid] * bk[c];
        sv += Wk[c * CDIM + tid] * bq[c];
    }
    g_wu[tid] = su;
    g_wv[tid] = sv;

    __shared__ float red[256];
    red[tid] = bq[tid] * bk[tid];
    __syncthreads();
    for (int s = 128; s > 0; s >>= 1) {
        if (tid < s) red[tid] += red[tid + s];
        __syncthreads();
    }
    if (tid == 0) g_cst = red[0];
}

// ---------------------------------------------------------------------------
// compute_uv: u[row] = Q[row].wu ; v[row] = K[row].wv  (rows = B*N = 8192)
// grid: 1024 blocks x 256 threads, one warp per row
// ---------------------------------------------------------------------------
__global__ void compute_uv(const float* __restrict__ Q, const float* __restrict__ K) {
    int warp = threadIdx.x >> 5;
    int lane = threadIdx.x & 31;
    int row = blockIdx.x * 8 + warp;
    const float* qr = Q + (size_t)row * CDIM;
    const float* kr = K + (size_t)row * CDIM;
    float au = 0.f, av = 0.f;
#pragma unroll
    for (int t = 0; t < 8; t++) {
        int c = lane + t * 32;
        au += qr[c] * g_wu[c];
        av += kr[c] * g_wv[c];
    }
#pragma unroll
    for (int o = 16; o > 0; o >>= 1) {
        au += __shfl_down_sync(0xffffffffu, au, o);
        av += __shfl_down_sync(0xffffffffu, av, o);
    }
    if (lane == 0) {
        g_u[row] = au;
        g_v[row] = av;
    }
}

// ---------------------------------------------------------------------------
// gemm_A: A[row, m] = sum_k Q[row,k] * Gt[m,k]    (8192 x 256 x 256, NT)
// grid: (4 m-tiles, 128 row-tiles), 256 threads, 64x64 tile, 4x4 micro
// ---------------------------------------------------------------------------
__global__ void gemm_A(const float* __restrict__ Q) {
    int mt = blockIdx.x;
    int rt = blockIdx.y;
    int tid = threadIdx.x;
    int tx = tid & 15;
    int ty = tid >> 4;
    int lr = tid >> 2;   // 0..63 : row within tile (loader)
    int lg = tid & 3;    // 0..3  : k-group of 4 (loader)

    __shared__ __align__(16) float As[16][64];  // [k][i]
    __shared__ __align__(16) float Bs[16][64];  // [k][m]

    const float* Ap = Q + (size_t)rt * 64 * CDIM;
    const float* Bp = g_Gt + (size_t)mt * 64 * CDIM;

    float acc[4][4] = {};
    for (int k0 = 0; k0 < CDIM; k0 += 16) {
        float4 a = *(const float4*)(Ap + (size_t)lr * CDIM + k0 + lg * 4);
        float4 bb = *(const float4*)(Bp + (size_t)lr * CDIM + k0 + lg * 4);
        As[lg * 4 + 0][lr] = a.x;  As[lg * 4 + 1][lr] = a.y;
        As[lg * 4 + 2][lr] = a.z;  As[lg * 4 + 3][lr] = a.w;
        Bs[lg * 4 + 0][lr] = bb.x; Bs[lg * 4 + 1][lr] = bb.y;
        Bs[lg * 4 + 2][lr] = bb.z; Bs[lg * 4 + 3][lr] = bb.w;
        __syncthreads();
#pragma unroll
        for (int kk = 0; kk < 16; kk++) {
            float4 av4 = *(const float4*)&As[kk][ty * 4];
            float4 bv4 = *(const float4*)&Bs[kk][tx * 4];
            float av[4] = {av4.x, av4.y, av4.z, av4.w};
            float bv[4] = {bv4.x, bv4.y, bv4.z, bv4.w};
#pragma unroll
            for (int ii = 0; ii < 4; ii++)
#pragma unroll
                for (int jj = 0; jj < 4; jj++)
                    acc[ii][jj] += av[ii] * bv[jj];
        }
        __syncthreads();
    }
    int row = rt * 64 + ty * 4;
    int m = mt * 64 + tx * 4;
#pragma unroll
    for (int ii = 0; ii < 4; ii++) {
        float4 o = {acc[ii][0], acc[ii][1], acc[ii][2], acc[ii][3]};
        *(float4*)&g_A[(size_t)(row + ii) * CDIM + m] = o;
    }
}

// ---------------------------------------------------------------------------
// main_fused: per block (b, it, jt):
//   scores_tile = A[b, i-tile, :] @ Key[b, j-tile, :]^T  (64x64x256 NT GEMM)
//   scores = (core + u[i] + v[j] + cst) / 16
//   out[b, r, i, j] = scores * R_map[i, j, r]   for r = 0..15
// grid: (8 batch  <- fastest, for R_map L2 reuse across b ; 256 tiles)
// ---------------------------------------------------------------------------
__global__ void main_fused(const float* __restrict__ Key,
                           const float* __restrict__ Rmap,
                           float* __restrict__ out) {
    int b = blockIdx.x;
    int tix = blockIdx.y;
    int it = tix >> 4;
    int jt = tix & 15;
    int tid = threadIdx.x;
    int tx = tid & 15;
    int ty = tid >> 4;
    int lr = tid >> 2;
    int lg = tid & 3;

    __shared__ __align__(16) float As[16][64];  // [k][i]
    __shared__ __align__(16) float Bs[16][64];  // [k][j]

    const float* Ap = g_A + ((size_t)b * N_SEQ + it * 64) * CDIM;
    const float* Bp = Key + ((size_t)b * N_SEQ + jt * 64) * CDIM;

    float acc[4][4] = {};
    for (int k0 = 0; k0 < CDIM; k0 += 16) {
        float4 a = *(const float4*)(Ap + (size_t)lr * CDIM + k0 + lg * 4);
        float4 bb = *(const float4*)(Bp + (size_t)lr * CDIM + k0 + lg * 4);
        As[lg * 4 + 0][lr] = a.x;  As[lg * 4 + 1][lr] = a.y;
        As[lg * 4 + 2][lr] = a.z;  As[lg * 4 + 3][lr] = a.w;
        Bs[lg * 4 + 0][lr] = bb.x; Bs[lg * 4 + 1][lr] = bb.y;
        Bs[lg * 4 + 2][lr] = bb.z; Bs[lg * 4 + 3][lr] = bb.w;
        __syncthreads();
#pragma unroll
        for (int kk = 0; kk < 16; kk++) {
            float4 av4 = *(const float4*)&As[kk][ty * 4];
            float4 bv4 = *(const float4*)&Bs[kk][tx * 4];
            float av[4] = {av4.x, av4.y, av4.z, av4.w};
            float bv[4] = {bv4.x, bv4.y, bv4.z, bv4.w};
#pragma unroll
            for (int ii = 0; ii < 4; ii++)
#pragma unroll
                for (int jj = 0; jj < 4; jj++)
                    acc[ii][jj] += av[ii] * bv[jj];
        }
        __syncthreads();
    }

    // epilogue: finalize scores
    int i0 = it * 64 + ty * 4;           // global i (0..1023)
    int j0 = jt * 64 + tx * 4;           // global j (0..1023)
    float cst = g_cst;
    float uu[4];
#pragma unroll
    for (int ii = 0; ii < 4; ii++) uu[ii] = g_u[b * N_SEQ + i0 + ii];
    float4 vv4 = *(const float4*)&g_v[b * N_SEQ + j0];
    float vvv[4] = {vv4.x, vv4.y, vv4.z, vv4.w};

    float s[4][4];
#pragma unroll
    for (int ii = 0; ii < 4; ii++)
#pragma unroll
        for (int jj = 0; jj < 4; jj++)
            s[ii][jj] = (acc[ii][jj] + uu[ii] + vvv[jj] + cst) * 0.0625f;

    // relation-mask multiply + store: 16 r values, vectorized over j and r
#pragma unroll
    for (int rg = 0; rg < 4; rg++) {
#pragma unroll
        for (int ii = 0; ii < 4; ii++) {
            int i = i0 + ii;
            const float* rp = Rmap + ((size_t)i * N_SEQ + j0) * RREL + rg * 4;
            float4 q0 = *(const float4*)(rp);
            float4 q1 = *(const float4*)(rp + RREL);
            float4 q2 = *(const float4*)(rp + 2 * RREL);
            float4 q3 = *(const float4*)(rp + 3 * RREL);
            float p0[4] = {q0.x, q0.y, q0.z, q0.w};
            float p1[4] = {q1.x, q1.y, q1.z, q1.w};
            float p2[4] = {q2.x, q2.y, q2.z, q2.w};
            float p3[4] = {q3.x, q3.y, q3.z, q3.w};
#pragma unroll
            for (int rr = 0; rr < 4; rr++) {
                int r = rg * 4 + rr;
                float4 o;
                o.x = s[ii][0] * p0[rr];
                o.y = s[ii][1] * p1[rr];
                o.z = s[ii][2] * p2[rr];
                o.w = s[ii][3] * p3[rr];
                size_t oidx = (((size_t)(b * RREL + r) * N_SEQ + i) * N_SEQ) + j0;
                *(float4*)(out + oidx) = o;
            }
        }
    }
}

// ---------------------------------------------------------------------------
extern "C" void kernel_launch(void* const* d_in, const int* in_sizes, int n_in,
                              void* d_out, int out_size) {
    const float* Q    = (const float*)d_in[0];  // (8,1024,256)
    const float* K    = (const float*)d_in[1];  // (8,1024,256)
    const float* Wq   = (const float*)d_in[2];  // (256,256)
    const float* bq   = (const float*)d_in[3];  // (256,)
    const float* Wk   = (const float*)d_in[4];  // (256,256)
    const float* bk   = (const float*)d_in[5];  // (256,)
    const float* Rmap = (const float*)d_in[6];  // (1024,1024,16)
    float* out = (float*)d_out;                 // (8,16,1024,1024)

    prep_gt<<<256, 256>>>(Wq, Wk);
    prep_vec<<<1, 256>>>(Wq, Wk, bq, bk);
    compute_uv<<<1024, 256>>>(Q, K);
    gemm_A<<<dim3(4, 128), 256>>>(Q);
    main_fused<<<dim3(8, 256), 256>>>(K, Rmap, out);
}